// round 5
// baseline (speedup 1.0000x reference)
#include <cuda_runtime.h>
#include <math.h>

#define BB      32
#define DIMM    4096
#define NH      32
#define NKV     8
#define HD      128
#define TSEQ    2048
#define NSPLIT  16
#define CHUNK   128      /* TSEQ / NSPLIT */
#define QK_SCALE 0.08838834764831845f  /* 128^-0.5 */

typedef unsigned long long u64;
union U64F2 { u64 u; float2 f; };

__device__ __forceinline__ u64 fma2(u64 a, u64 b, u64 c) {
    u64 d;
    asm("fma.rn.f32x2 %0, %1, %2, %3;" : "=l"(d) : "l"(a), "l"(b), "l"(c));
    return d;
}
__device__ __forceinline__ u64 pack2(float lo, float hi) {
    u64 d;
    asm("mov.b64 %0, {%1, %2};" : "=l"(d) : "f"(lo), "f"(hi));
    return d;
}

// ------------------------- scratch (device globals) -------------------------
__device__ float g_q[BB * NH * HD];            // roped Q   [b][h][d]
__device__ float g_k[BB * NKV * HD];           // roped K @ pos 2047 [b][kv][d]
__device__ float g_v[BB * NKV * HD];           // V       @ pos 2047 [b][kv][d]
__device__ float g_att[BB * DIMM];             // attention output [b][h*128+d]
__device__ float g_part[BB * NH * NSPLIT * HD];
__device__ float g_ml[BB * NH * NSPLIT * 2];   // (m, l) per split

// ---------------------------------------------------------------------------
// GEMM: out[m][n] = sum_k x[m][k] * w[n][k];  M = 32 (batch), K = 4096.
// Lanes span m (batch): lane l owns row m=l for the warp's 4 columns.
//   -> acc = 4 packed f32x2 accumulators (k-parity split), no cross-lane
//      reduction, low regs -> high occupancy.
// x staged in smem TRANSPOSED as float2 k-pairs: xt2[kpair][m]. Main-loop
//   LDS.64 (lane -> consecutive float2) is conflict-free and delivers the
//   (x[k], x[k+1]) operand pre-packed for fma.rn.f32x2.
// w: 4 rows per warp, LDG.128 broadcast (all lanes same address).
// MODE 0: fused QKV + RoPE epilogue -> g_q / g_k / g_v
// MODE 1: x = g_att, w = wo, plain write to out
// ---------------------------------------------------------------------------
template <int MODE>
__global__ __launch_bounds__(128) void gemm_kernel(
    const float* __restrict__ x,
    const float* __restrict__ wq, const float* __restrict__ wk,
    const float* __restrict__ wv,
    const float* __restrict__ fc, const float* __restrict__ fs,
    float* __restrict__ out)
{
    __shared__ float2 xt2[128 * 32];   // 32 KB: [kpair within tile][m]

    const int tid  = threadIdx.x;
    const int lane = tid & 31;
    const int warp = tid >> 5;
    const int nblk = blockIdx.x * 16;
    const int n0   = nblk + warp * 4;

    const float* w;
    int nrel;
    if (MODE == 0) {
        if (nblk < 4096)      { w = wq; nrel = n0; }
        else if (nblk < 5120) { w = wk; nrel = n0 - 4096; }
        else                  { w = wv; nrel = n0 - 5120; }
    } else { w = wq; nrel = n0; }

    const float4* w0 = (const float4*)(w + (size_t)(nrel + 0) * 4096);
    const float4* w1 = (const float4*)(w + (size_t)(nrel + 1) * 4096);
    const float4* w2 = (const float4*)(w + (size_t)(nrel + 2) * 4096);
    const float4* w3 = (const float4*)(w + (size_t)(nrel + 3) * 4096);
    const float4* xg = (const float4*)((MODE == 1) ? (const float*)g_att : x);

    u64 acc0 = 0ull, acc1 = 0ull, acc2 = 0ull, acc3 = 0ull;

    for (int tile = 0; tile < 16; ++tile) {
        __syncthreads();
        // load x tile transposed: 32 m x 256 k -> xt2[kpair][m]
#pragma unroll
        for (int j = 0; j < 8; j++) {
            int idx = j * 128 + tid;        // 0..1023 over (m, k-oct)
            int m   = idx & 31;
            int ko  = idx >> 5;             // 0..31 (pairs of quads)
            float4 v0 = xg[m * 1024 + tile * 64 + ko * 2];
            float4 v1 = xg[m * 1024 + tile * 64 + ko * 2 + 1];
            xt2[(ko * 4 + 0) * 32 + m] = make_float2(v0.x, v0.y);
            xt2[(ko * 4 + 1) * 32 + m] = make_float2(v0.z, v0.w);
            xt2[(ko * 4 + 2) * 32 + m] = make_float2(v1.x, v1.y);
            xt2[(ko * 4 + 3) * 32 + m] = make_float2(v1.z, v1.w);
        }
        __syncthreads();

        const float4* w0t = w0 + tile * 64;
        const float4* w1t = w1 + tile * 64;
        const float4* w2t = w2 + tile * 64;
        const float4* w3t = w3 + tile * 64;
#pragma unroll 8
        for (int kq = 0; kq < 64; kq++) {
            float4 a = w0t[kq], b = w1t[kq], c = w2t[kq], d = w3t[kq];
            u64 x01 = *(const u64*)(&xt2[(kq * 2)     * 32 + lane]);
            u64 x23 = *(const u64*)(&xt2[(kq * 2 + 1) * 32 + lane]);
            acc0 = fma2(pack2(a.x, a.y), x01, acc0);
            acc0 = fma2(pack2(a.z, a.w), x23, acc0);
            acc1 = fma2(pack2(b.x, b.y), x01, acc1);
            acc1 = fma2(pack2(b.z, b.w), x23, acc1);
            acc2 = fma2(pack2(c.x, c.y), x01, acc2);
            acc2 = fma2(pack2(c.z, c.w), x23, acc2);
            acc3 = fma2(pack2(d.x, d.y), x01, acc3);
            acc3 = fma2(pack2(d.z, d.w), x23, acc3);
        }
    }

    // collapse k-parity halves; lane l holds batch row m = l, 4 columns.
    U64F2 u0, u1, u2, u3;
    u0.u = acc0; u1.u = acc1; u2.u = acc2; u3.u = acc3;
    float4 res;
    res.x = u0.f.x + u0.f.y;
    res.y = u1.f.x + u1.f.y;
    res.z = u2.f.x + u2.f.y;
    res.w = u3.f.x + u3.f.y;
    const int m = lane;

    if (MODE == 1) {
        *(float4*)(out + (size_t)m * 4096 + n0) = res;
    } else {
        if (n0 < 4096) {            // Q + RoPE
            int h = n0 >> 7, d = n0 & 127;
            int i0 = d >> 1;
            float c0 = fc[i0], s0 = fs[i0], c1 = fc[i0 + 1], s1 = fs[i0 + 1];
            float4 o;
            o.x = res.x * c0 - res.y * s0;
            o.y = res.x * s0 + res.y * c0;
            o.z = res.z * c1 - res.w * s1;
            o.w = res.z * s1 + res.w * c1;
            *(float4*)(&g_q[(m * NH + h) * HD + d]) = o;
        } else if (n0 < 5120) {     // K + RoPE
            int nk = n0 - 4096;
            int h = nk >> 7, d = nk & 127;
            int i0 = d >> 1;
            float c0 = fc[i0], s0 = fs[i0], c1 = fc[i0 + 1], s1 = fs[i0 + 1];
            float4 o;
            o.x = res.x * c0 - res.y * s0;
            o.y = res.x * s0 + res.y * c0;
            o.z = res.z * c1 - res.w * s1;
            o.w = res.z * s1 + res.w * c1;
            *(float4*)(&g_k[(m * NKV + h) * HD + d]) = o;
        } else {                    // V passthrough
            int nv = n0 - 5120;
            int h = nv >> 7, d = nv & 127;
            *(float4*)(&g_v[(m * NKV + h) * HD + d]) = res;
        }
    }
}

// ---------------------------------------------------------------------------
// Split-sequence flash decode. Grid = B*NKV*NSPLIT blocks of 256 threads.
// Position 2047 comes from the freshly roped g_k/g_v (cache row is stale).
// ---------------------------------------------------------------------------
__global__ __launch_bounds__(256) void attn_kernel(
    const float* __restrict__ ck, const float* __restrict__ cv)
{
    __shared__ float  s_sc[4 * CHUNK];     // scores -> exp(p)
    __shared__ float  s_ml[8];
    __shared__ float4 s_red[8 * 4 * 32];   // 16 KB: [pg][h][dquad]

    const int bid   = blockIdx.x;
    const int split = bid % NSPLIT;
    const int kv    = (bid / NSPLIT) % NKV;
    const int b     = bid / (NSPLIT * NKV);
    const int tid   = threadIdx.x;
    const int lane  = tid & 31;
    const int warp  = tid >> 5;
    const int t0    = split * CHUNK;
    const bool last = (split == NSPLIT - 1);
    const int nmain = last ? CHUNK - 1 : CHUNK;

    // ---- phase 1: scores; warp handles 4 positions per outer iteration ----
    const float4* qg = (const float4*)g_q;
    const int qb = (b * NH + kv * 4) * 32;
    float4 q0 = qg[qb + 0 * 32 + lane];
    float4 q1 = qg[qb + 1 * 32 + lane];
    float4 q2 = qg[qb + 2 * 32 + lane];
    float4 q3 = qg[qb + 3 * 32 + lane];

    const float4* kg = (const float4*)ck
                     + (size_t)(b * TSEQ + t0) * (NKV * 32) + kv * 32 + lane;
#pragma unroll
    for (int base = warp * 4; base < CHUNK; base += 32) {
        float4 k4[4];
#pragma unroll
        for (int j = 0; j < 4; j++)
            k4[j] = kg[(size_t)(base + j) * (NKV * 32)];

        float s[16];
#pragma unroll
        for (int j = 0; j < 4; j++) {
            s[j*4+0] = fmaf(k4[j].x, q0.x, fmaf(k4[j].y, q0.y, fmaf(k4[j].z, q0.z, k4[j].w * q0.w)));
            s[j*4+1] = fmaf(k4[j].x, q1.x, fmaf(k4[j].y, q1.y, fmaf(k4[j].z, q1.z, k4[j].w * q1.w)));
            s[j*4+2] = fmaf(k4[j].x, q2.x, fmaf(k4[j].y, q2.y, fmaf(k4[j].z, q2.z, k4[j].w * q2.w)));
            s[j*4+3] = fmaf(k4[j].x, q3.x, fmaf(k4[j].y, q3.y, fmaf(k4[j].z, q3.z, k4[j].w * q3.w)));
        }
#pragma unroll
        for (int o = 16; o; o >>= 1) {
#pragma unroll
            for (int v = 0; v < 16; v++)
                s[v] += __shfl_xor_sync(0xffffffffu, s[v], o);
        }
        if (lane == 0) {
#pragma unroll
            for (int j = 0; j < 4; j++) {
                if (base + j < nmain) {
                    s_sc[0 * CHUNK + base + j] = s[j*4+0] * QK_SCALE;
                    s_sc[1 * CHUNK + base + j] = s[j*4+1] * QK_SCALE;
                    s_sc[2 * CHUNK + base + j] = s[j*4+2] * QK_SCALE;
                    s_sc[3 * CHUNK + base + j] = s[j*4+3] * QK_SCALE;
                }
            }
        }
    }
    if (last && warp == 7) {   // position 2047 from roped scratch
        const float4* kg2 = (const float4*)g_k;
        float4 k4 = kg2[(b * NKV + kv) * 32 + lane];
        float s0 = q0.x * k4.x + q0.y * k4.y + q0.z * k4.z + q0.w * k4.w;
        float s1 = q1.x * k4.x + q1.y * k4.y + q1.z * k4.z + q1.w * k4.w;
        float s2 = q2.x * k4.x + q2.y * k4.y + q2.z * k4.z + q2.w * k4.w;
        float s3 = q3.x * k4.x + q3.y * k4.y + q3.z * k4.z + q3.w * k4.w;
#pragma unroll
        for (int o = 16; o; o >>= 1) {
            s0 += __shfl_xor_sync(0xffffffffu, s0, o);
            s1 += __shfl_xor_sync(0xffffffffu, s1, o);
            s2 += __shfl_xor_sync(0xffffffffu, s2, o);
            s3 += __shfl_xor_sync(0xffffffffu, s3, o);
        }
        if (lane == 0) {
            s_sc[0 * CHUNK + CHUNK - 1] = s0 * QK_SCALE;
            s_sc[1 * CHUNK + CHUNK - 1] = s1 * QK_SCALE;
            s_sc[2 * CHUNK + CHUNK - 1] = s2 * QK_SCALE;
            s_sc[3 * CHUNK + CHUNK - 1] = s3 * QK_SCALE;
        }
    }
    __syncthreads();

    // ---- phase 2: local softmax (warp r handles row r) ----
    if (warp < 4) {
        float* row = s_sc + warp * CHUNK;
        float v[CHUNK / 32];
        float mx = -1e30f;
#pragma unroll
        for (int j = 0; j < CHUNK / 32; j++) { v[j] = row[lane + 32 * j]; mx = fmaxf(mx, v[j]); }
#pragma unroll
        for (int o = 16; o; o >>= 1) mx = fmaxf(mx, __shfl_xor_sync(0xffffffffu, mx, o));
        float sum = 0.f;
#pragma unroll
        for (int j = 0; j < CHUNK / 32; j++) {
            float p = __expf(v[j] - mx);
            row[lane + 32 * j] = p;
            sum += p;
        }
#pragma unroll
        for (int o = 16; o; o >>= 1) sum += __shfl_xor_sync(0xffffffffu, sum, o);
        if (lane == 0) { s_ml[warp * 2] = mx; s_ml[warp * 2 + 1] = sum; }
    }
    __syncthreads();

    // ---- phase 3: P @ V (warp = pos-group, lane = d-quad) ----
    {
        const int pg = warp;
        const int dq = lane;
        float4 a0 = make_float4(0.f,0.f,0.f,0.f);
        float4 a1 = a0, a2 = a0, a3 = a0;
        const float4* vb = (const float4*)cv
                         + (size_t)(b * TSEQ + t0) * (NKV * 32) + kv * 32 + dq;
        const float* p0r = s_sc + 0 * CHUNK;
        const float* p1r = s_sc + 1 * CHUNK;
        const float* p2r = s_sc + 2 * CHUNK;
        const float* p3r = s_sc + 3 * CHUNK;
#pragma unroll 4
        for (int i = pg; i < nmain; i += 8) {
            float4 v4 = vb[(size_t)i * (NKV * 32)];
            float p0 = p0r[i], p1 = p1r[i], p2 = p2r[i], p3 = p3r[i];
            a0.x = fmaf(p0, v4.x, a0.x); a0.y = fmaf(p0, v4.y, a0.y);
            a0.z = fmaf(p0, v4.z, a0.z); a0.w = fmaf(p0, v4.w, a0.w);
            a1.x = fmaf(p1, v4.x, a1.x); a1.y = fmaf(p1, v4.y, a1.y);
            a1.z = fmaf(p1, v4.z, a1.z); a1.w = fmaf(p1, v4.w, a1.w);
            a2.x = fmaf(p2, v4.x, a2.x); a2.y = fmaf(p2, v4.y, a2.y);
            a2.z = fmaf(p2, v4.z, a2.z); a2.w = fmaf(p2, v4.w, a2.w);
            a3.x = fmaf(p3, v4.x, a3.x); a3.y = fmaf(p3, v4.y, a3.y);
            a3.z = fmaf(p3, v4.z, a3.z); a3.w = fmaf(p3, v4.w, a3.w);
        }
        s_red[(pg * 4 + 0) * 32 + dq] = a0;
        s_red[(pg * 4 + 1) * 32 + dq] = a1;
        s_red[(pg * 4 + 2) * 32 + dq] = a2;
        s_red[(pg * 4 + 3) * 32 + dq] = a3;
    }
    __syncthreads();

    // cross-pos-group reduction + last-position term
    if (tid < 128) {
        const int h  = tid >> 5;
        const int dq = tid & 31;
        float4 s = make_float4(0.f, 0.f, 0.f, 0.f);
#pragma unroll
        for (int pg = 0; pg < 8; pg++) {
            float4 t = s_red[(pg * 4 + h) * 32 + dq];
            s.x += t.x; s.y += t.y; s.z += t.z; s.w += t.w;
        }
        if (last) {
            float4 v4 = ((const float4*)g_v)[(b * NKV + kv) * 32 + dq];
            float p = s_sc[h * CHUNK + CHUNK - 1];
            s.x = fmaf(p, v4.x, s.x); s.y = fmaf(p, v4.y, s.y);
            s.z = fmaf(p, v4.z, s.z); s.w = fmaf(p, v4.w, s.w);
        }
        float4* gp = (float4*)g_part;
        gp[((size_t)(b * NH + kv * 4 + h) * NSPLIT + split) * 32 + dq] = s;
    }
    if (tid < 8) {
        int r = tid >> 1;
        g_ml[((b * NH + kv * 4 + r) * NSPLIT + split) * 2 + (tid & 1)] = s_ml[tid];
    }
}

// ---------------------------------------------------------------------------
// Combine split partials (log-sum-exp). Grid = B*NH blocks of 128 threads.
// ---------------------------------------------------------------------------
__global__ __launch_bounds__(128) void reduce_kernel()
{
    const int hg = blockIdx.x;        // b*NH + h
    const int d  = threadIdx.x;
    float ms[NSPLIT], ls[NSPLIT];
    float m = -1e30f;
#pragma unroll
    for (int i = 0; i < NSPLIT; i++) {
        ms[i] = g_ml[(hg * NSPLIT + i) * 2];
        ls[i] = g_ml[(hg * NSPLIT + i) * 2 + 1];
        m = fmaxf(m, ms[i]);
    }
    float num = 0.f, den = 0.f;
#pragma unroll
    for (int i = 0; i < NSPLIT; i++) {
        float wgt = __expf(ms[i] - m);
        den += wgt * ls[i];
        num += wgt * g_part[((size_t)hg * NSPLIT + i) * HD + d];
    }
    const int b = hg >> 5, h = hg & 31;
    g_att[b * DIMM + h * HD + d] = num / den;
}

// ---------------------------------------------------------------------------
extern "C" void kernel_launch(void* const* d_in, const int* in_sizes, int n_in,
                              void* d_out, int out_size)
{
    const float* x  = (const float*)d_in[0];
    const float* fc = (const float*)d_in[1];
    const float* fs = (const float*)d_in[2];
    const float* wq = (const float*)d_in[3];
    const float* wk = (const float*)d_in[4];
    const float* wv = (const float*)d_in[5];
    const float* wo = (const float*)d_in[6];
    const float* ck = (const float*)d_in[7];
    const float* cv = (const float*)d_in[8];
    float* out = (float*)d_out;

    gemm_kernel<0><<<6144 / 16, 128>>>(x, wq, wk, wv, fc, fs, nullptr);
    attn_kernel<<<BB * NKV * NSPLIT, 256>>>(ck, cv);
    reduce_kernel<<<BB * NH, 128>>>();
    gemm_kernel<1><<<4096 / 16, 128>>>(nullptr, wo, nullptr, nullptr, nullptr, nullptr, out);
}

// round 6
// speedup vs baseline: 2.6776x; 2.6776x over previous
#include <cuda_runtime.h>
#include <math.h>

#define BB      32
#define DIMM    4096
#define NH      32
#define NKV     8
#define HD      128
#define TSEQ    2048
#define NSPLIT  16
#define CHUNK   128      /* TSEQ / NSPLIT */
#define QK_SCALE 0.08838834764831845f  /* 128^-0.5 */

// ------------------------- scratch (device globals) -------------------------
__device__ float g_q[BB * NH * HD];            // roped Q   [b][h][d]
__device__ float g_k[BB * NKV * HD];           // roped K @ pos 2047 [b][kv][d]
__device__ float g_v[BB * NKV * HD];           // V       @ pos 2047 [b][kv][d]
__device__ float g_att[BB * DIMM];             // attention output [b][h*128+d]
__device__ float g_part[BB * NH * NSPLIT * HD];
__device__ float g_ml[BB * NH * NSPLIT * 2];   // (m, l) per split

// ---------------------------------------------------------------------------
// GEMM v3: out[m][n] = sum_k x[m][k] * w[n][k];  M = 32, K = 4096.
// 128 thr / 4 warps, 2 cols per warp -> 8 cols/CTA (grid 768 / 512).
// Lanes span k: coalesced 512B w loads; software pipeline keeps the next
// tile's 4 w lines in flight during current-tile FMAs (MLP >= 4/warp).
// acc[32] float2 (m x 2 cols) ~ 120 regs -> 4 CTAs/SM.
// x staged in 32KB smem tiles (256 k), 8 FFMA per LDS.128 (crossbar at cap).
// Epilogue: log-step shuffle halving -> lane l holds batch m=l; 2 cols =
// one RoPE (even, odd) pair.
// MODE 0: fused QKV + RoPE -> g_q/g_k/g_v.  MODE 1: g_att @ wo -> out.
// ---------------------------------------------------------------------------
template <int MODE>
__global__ __launch_bounds__(128) void gemm_kernel(
    const float* __restrict__ x,
    const float* __restrict__ wq, const float* __restrict__ wk,
    const float* __restrict__ wv,
    const float* __restrict__ fc, const float* __restrict__ fs,
    float* __restrict__ out)
{
    __shared__ float4 xs4[32 * 64];   // 32 KB: x tile [m][64 float4 = 256 k]

    const int tid  = threadIdx.x;
    const int lane = tid & 31;
    const int warp = tid >> 5;
    const int nblk = blockIdx.x * 8;
    const int n0   = nblk + warp * 2;

    const float* w;
    int nrel;
    if (MODE == 0) {
        if (nblk < 4096)      { w = wq; nrel = n0; }
        else if (nblk < 5120) { w = wk; nrel = n0 - 4096; }
        else                  { w = wv; nrel = n0 - 5120; }
    } else { w = wq; nrel = n0; }

    const float4* w0 = (const float4*)(w + (size_t)(nrel + 0) * 4096);
    const float4* w1 = (const float4*)(w + (size_t)(nrel + 1) * 4096);
    const float4* xg = (const float4*)((MODE == 1) ? (const float*)g_att : x);

    float2 acc[32];
#pragma unroll
    for (int m = 0; m < 32; m++) acc[m] = make_float2(0.f, 0.f);

    // prime the w pipeline (tile 0: both r-steps, both cols)
    float4 a0 = w0[lane], a1 = w0[32 + lane];
    float4 b0 = w1[lane], b1 = w1[32 + lane];

    for (int tile = 0; tile < 16; ++tile) {
        __syncthreads();
#pragma unroll
        for (int j = 0; j < 16; j++) {
            int idx = tid + j * 128;            // 0..2047 float4s
            int m   = idx >> 6;
            int kk  = idx & 63;
            xs4[idx] = xg[m * 1024 + tile * 64 + kk];
        }
        __syncthreads();

        // issue next tile's w loads before the FMA block
        float4 na0, na1, nb0, nb1;
        if (tile < 15) {
            const float4* w0n = w0 + (tile + 1) * 64;
            const float4* w1n = w1 + (tile + 1) * 64;
            na0 = w0n[lane]; na1 = w0n[32 + lane];
            nb0 = w1n[lane]; nb1 = w1n[32 + lane];
        } else {
            na0 = na1 = nb0 = nb1 = make_float4(0.f, 0.f, 0.f, 0.f);
        }

#pragma unroll
        for (int r = 0; r < 2; r++) {
            float4 wa = r ? a1 : a0;
            float4 wb = r ? b1 : b0;
#pragma unroll
            for (int m = 0; m < 32; m++) {
                float4 xv = xs4[m * 64 + r * 32 + lane];
                acc[m].x = fmaf(xv.x, wa.x, fmaf(xv.y, wa.y, fmaf(xv.z, wa.z, fmaf(xv.w, wa.w, acc[m].x))));
                acc[m].y = fmaf(xv.x, wb.x, fmaf(xv.y, wb.y, fmaf(xv.z, wb.z, fmaf(xv.w, wb.w, acc[m].y))));
            }
        }
        a0 = na0; a1 = na1; b0 = nb0; b1 = nb1;
    }

    // log-step shuffle halving: lane l -> totals for batch m = l
#pragma unroll
    for (int step = 16; step >= 1; step >>= 1) {
        bool hi = (lane & step) != 0;
#pragma unroll
        for (int i = 0; i < step; i++) {
            float2 s = hi ? acc[i] : acc[i + step];
            float2 k = hi ? acc[i + step] : acc[i];
            float2 r;
            r.x = k.x + __shfl_xor_sync(0xffffffffu, s.x, step);
            r.y = k.y + __shfl_xor_sync(0xffffffffu, s.y, step);
            acc[i] = r;
        }
    }
    float2 res = acc[0];   // columns n0, n0+1 for batch m = lane
    const int m = lane;

    if (MODE == 1) {
        *(float2*)(out + (size_t)m * 4096 + n0) = res;
    } else {
        if (n0 < 4096) {            // Q + RoPE
            int h = n0 >> 7, d = n0 & 127;
            int i0 = d >> 1;
            float c0 = fc[i0], s0 = fs[i0];
            float2 o;
            o.x = res.x * c0 - res.y * s0;
            o.y = res.x * s0 + res.y * c0;
            *(float2*)(&g_q[(m * NH + h) * HD + d]) = o;
        } else if (n0 < 5120) {     // K + RoPE
            int nk = n0 - 4096;
            int h = nk >> 7, d = nk & 127;
            int i0 = d >> 1;
            float c0 = fc[i0], s0 = fs[i0];
            float2 o;
            o.x = res.x * c0 - res.y * s0;
            o.y = res.x * s0 + res.y * c0;
            *(float2*)(&g_k[(m * NKV + h) * HD + d]) = o;
        } else {                    // V passthrough
            int nv = n0 - 5120;
            int h = nv >> 7, d = nv & 127;
            *(float2*)(&g_v[(m * NKV + h) * HD + d]) = res;
        }
    }
}

// ---------------------------------------------------------------------------
// Split-sequence flash decode. Grid = B*NKV*NSPLIT blocks of 256 threads.
// (byte-identical to the R5-validated version)
// ---------------------------------------------------------------------------
__global__ __launch_bounds__(256) void attn_kernel(
    const float* __restrict__ ck, const float* __restrict__ cv)
{
    __shared__ float  s_sc[4 * CHUNK];     // scores -> exp(p)
    __shared__ float  s_ml[8];
    __shared__ float4 s_red[8 * 4 * 32];   // 16 KB: [pg][h][dquad]

    const int bid   = blockIdx.x;
    const int split = bid % NSPLIT;
    const int kv    = (bid / NSPLIT) % NKV;
    const int b     = bid / (NSPLIT * NKV);
    const int tid   = threadIdx.x;
    const int lane  = tid & 31;
    const int warp  = tid >> 5;
    const int t0    = split * CHUNK;
    const bool last = (split == NSPLIT - 1);
    const int nmain = last ? CHUNK - 1 : CHUNK;

    // ---- phase 1: scores; warp handles 4 positions per outer iteration ----
    const float4* qg = (const float4*)g_q;
    const int qb = (b * NH + kv * 4) * 32;
    float4 q0 = qg[qb + 0 * 32 + lane];
    float4 q1 = qg[qb + 1 * 32 + lane];
    float4 q2 = qg[qb + 2 * 32 + lane];
    float4 q3 = qg[qb + 3 * 32 + lane];

    const float4* kg = (const float4*)ck
                     + (size_t)(b * TSEQ + t0) * (NKV * 32) + kv * 32 + lane;
#pragma unroll
    for (int base = warp * 4; base < CHUNK; base += 32) {
        float4 k4[4];
#pragma unroll
        for (int j = 0; j < 4; j++)
            k4[j] = kg[(size_t)(base + j) * (NKV * 32)];

        float s[16];
#pragma unroll
        for (int j = 0; j < 4; j++) {
            s[j*4+0] = fmaf(k4[j].x, q0.x, fmaf(k4[j].y, q0.y, fmaf(k4[j].z, q0.z, k4[j].w * q0.w)));
            s[j*4+1] = fmaf(k4[j].x, q1.x, fmaf(k4[j].y, q1.y, fmaf(k4[j].z, q1.z, k4[j].w * q1.w)));
            s[j*4+2] = fmaf(k4[j].x, q2.x, fmaf(k4[j].y, q2.y, fmaf(k4[j].z, q2.z, k4[j].w * q2.w)));
            s[j*4+3] = fmaf(k4[j].x, q3.x, fmaf(k4[j].y, q3.y, fmaf(k4[j].z, q3.z, k4[j].w * q3.w)));
        }
#pragma unroll
        for (int o = 16; o; o >>= 1) {
#pragma unroll
            for (int v = 0; v < 16; v++)
                s[v] += __shfl_xor_sync(0xffffffffu, s[v], o);
        }
        if (lane == 0) {
#pragma unroll
            for (int j = 0; j < 4; j++) {
                if (base + j < nmain) {
                    s_sc[0 * CHUNK + base + j] = s[j*4+0] * QK_SCALE;
                    s_sc[1 * CHUNK + base + j] = s[j*4+1] * QK_SCALE;
                    s_sc[2 * CHUNK + base + j] = s[j*4+2] * QK_SCALE;
                    s_sc[3 * CHUNK + base + j] = s[j*4+3] * QK_SCALE;
                }
            }
        }
    }
    if (last && warp == 7) {   // position 2047 from roped scratch
        const float4* kg2 = (const float4*)g_k;
        float4 k4 = kg2[(b * NKV + kv) * 32 + lane];
        float s0 = q0.x * k4.x + q0.y * k4.y + q0.z * k4.z + q0.w * k4.w;
        float s1 = q1.x * k4.x + q1.y * k4.y + q1.z * k4.z + q1.w * k4.w;
        float s2 = q2.x * k4.x + q2.y * k4.y + q2.z * k4.z + q2.w * k4.w;
        float s3 = q3.x * k4.x + q3.y * k4.y + q3.z * k4.z + q3.w * k4.w;
#pragma unroll
        for (int o = 16; o; o >>= 1) {
            s0 += __shfl_xor_sync(0xffffffffu, s0, o);
            s1 += __shfl_xor_sync(0xffffffffu, s1, o);
            s2 += __shfl_xor_sync(0xffffffffu, s2, o);
            s3 += __shfl_xor_sync(0xffffffffu, s3, o);
        }
        if (lane == 0) {
            s_sc[0 * CHUNK + CHUNK - 1] = s0 * QK_SCALE;
            s_sc[1 * CHUNK + CHUNK - 1] = s1 * QK_SCALE;
            s_sc[2 * CHUNK + CHUNK - 1] = s2 * QK_SCALE;
            s_sc[3 * CHUNK + CHUNK - 1] = s3 * QK_SCALE;
        }
    }
    __syncthreads();

    // ---- phase 2: local softmax (warp r handles row r) ----
    if (warp < 4) {
        float* row = s_sc + warp * CHUNK;
        float v[CHUNK / 32];
        float mx = -1e30f;
#pragma unroll
        for (int j = 0; j < CHUNK / 32; j++) { v[j] = row[lane + 32 * j]; mx = fmaxf(mx, v[j]); }
#pragma unroll
        for (int o = 16; o; o >>= 1) mx = fmaxf(mx, __shfl_xor_sync(0xffffffffu, mx, o));
        float sum = 0.f;
#pragma unroll
        for (int j = 0; j < CHUNK / 32; j++) {
            float p = __expf(v[j] - mx);
            row[lane + 32 * j] = p;
            sum += p;
        }
#pragma unroll
        for (int o = 16; o; o >>= 1) sum += __shfl_xor_sync(0xffffffffu, sum, o);
        if (lane == 0) { s_ml[warp * 2] = mx; s_ml[warp * 2 + 1] = sum; }
    }
    __syncthreads();

    // ---- phase 3: P @ V (warp = pos-group, lane = d-quad) ----
    {
        const int pg = warp;
        const int dq = lane;
        float4 a0 = make_float4(0.f,0.f,0.f,0.f);
        float4 a1 = a0, a2 = a0, a3 = a0;
        const float4* vb = (const float4*)cv
                         + (size_t)(b * TSEQ + t0) * (NKV * 32) + kv * 32 + dq;
        const float* p0r = s_sc + 0 * CHUNK;
        const float* p1r = s_sc + 1 * CHUNK;
        const float* p2r = s_sc + 2 * CHUNK;
        const float* p3r = s_sc + 3 * CHUNK;
#pragma unroll 4
        for (int i = pg; i < nmain; i += 8) {
            float4 v4 = vb[(size_t)i * (NKV * 32)];
            float p0 = p0r[i], p1 = p1r[i], p2 = p2r[i], p3 = p3r[i];
            a0.x = fmaf(p0, v4.x, a0.x); a0.y = fmaf(p0, v4.y, a0.y);
            a0.z = fmaf(p0, v4.z, a0.z); a0.w = fmaf(p0, v4.w, a0.w);
            a1.x = fmaf(p1, v4.x, a1.x); a1.y = fmaf(p1, v4.y, a1.y);
            a1.z = fmaf(p1, v4.z, a1.z); a1.w = fmaf(p1, v4.w, a1.w);
            a2.x = fmaf(p2, v4.x, a2.x); a2.y = fmaf(p2, v4.y, a2.y);
            a2.z = fmaf(p2, v4.z, a2.z); a2.w = fmaf(p2, v4.w, a2.w);
            a3.x = fmaf(p3, v4.x, a3.x); a3.y = fmaf(p3, v4.y, a3.y);
            a3.z = fmaf(p3, v4.z, a3.z); a3.w = fmaf(p3, v4.w, a3.w);
        }
        s_red[(pg * 4 + 0) * 32 + dq] = a0;
        s_red[(pg * 4 + 1) * 32 + dq] = a1;
        s_red[(pg * 4 + 2) * 32 + dq] = a2;
        s_red[(pg * 4 + 3) * 32 + dq] = a3;
    }
    __syncthreads();

    // cross-pos-group reduction + last-position term
    if (tid < 128) {
        const int h  = tid >> 5;
        const int dq = tid & 31;
        float4 s = make_float4(0.f, 0.f, 0.f, 0.f);
#pragma unroll
        for (int pg = 0; pg < 8; pg++) {
            float4 t = s_red[(pg * 4 + h) * 32 + dq];
            s.x += t.x; s.y += t.y; s.z += t.z; s.w += t.w;
        }
        if (last) {
            float4 v4 = ((const float4*)g_v)[(b * NKV + kv) * 32 + dq];
            float p = s_sc[h * CHUNK + CHUNK - 1];
            s.x = fmaf(p, v4.x, s.x); s.y = fmaf(p, v4.y, s.y);
            s.z = fmaf(p, v4.z, s.z); s.w = fmaf(p, v4.w, s.w);
        }
        float4* gp = (float4*)g_part;
        gp[((size_t)(b * NH + kv * 4 + h) * NSPLIT + split) * 32 + dq] = s;
    }
    if (tid < 8) {
        int r = tid >> 1;
        g_ml[((b * NH + kv * 4 + r) * NSPLIT + split) * 2 + (tid & 1)] = s_ml[tid];
    }
}

// ---------------------------------------------------------------------------
// Combine split partials (log-sum-exp). Grid = B*NH blocks of 128 threads.
// ---------------------------------------------------------------------------
__global__ __launch_bounds__(128) void reduce_kernel()
{
    const int hg = blockIdx.x;        // b*NH + h
    const int d  = threadIdx.x;
    float ms[NSPLIT], ls[NSPLIT];
    float m = -1e30f;
#pragma unroll
    for (int i = 0; i < NSPLIT; i++) {
        ms[i] = g_ml[(hg * NSPLIT + i) * 2];
        ls[i] = g_ml[(hg * NSPLIT + i) * 2 + 1];
        m = fmaxf(m, ms[i]);
    }
    float num = 0.f, den = 0.f;
#pragma unroll
    for (int i = 0; i < NSPLIT; i++) {
        float wgt = __expf(ms[i] - m);
        den += wgt * ls[i];
        num += wgt * g_part[((size_t)hg * NSPLIT + i) * HD + d];
    }
    const int b = hg >> 5, h = hg & 31;
    g_att[b * DIMM + h * HD + d] = num / den;
}

// ---------------------------------------------------------------------------
extern "C" void kernel_launch(void* const* d_in, const int* in_sizes, int n_in,
                              void* d_out, int out_size)
{
    const float* x  = (const float*)d_in[0];
    const float* fc = (const float*)d_in[1];
    const float* fs = (const float*)d_in[2];
    const float* wq = (const float*)d_in[3];
    const float* wk = (const float*)d_in[4];
    const float* wv = (const float*)d_in[5];
    const float* wo = (const float*)d_in[6];
    const float* ck = (const float*)d_in[7];
    const float* cv = (const float*)d_in[8];
    float* out = (float*)d_out;

    gemm_kernel<0><<<6144 / 8, 128>>>(x, wq, wk, wv, fc, fs, nullptr);
    attn_kernel<<<BB * NKV * NSPLIT, 256>>>(ck, cv);
    reduce_kernel<<<BB * NH, 128>>>();
    gemm_kernel<1><<<4096 / 8, 128>>>(nullptr, wo, nullptr, nullptr, nullptr, nullptr, out);
}

// round 8
// speedup vs baseline: 3.3784x; 1.2617x over previous
#include <cuda_runtime.h>
#include <math.h>

#define BB      32
#define DIMM    4096
#define NH      32
#define NKV     8
#define HD      128
#define TSEQ    2048
#define NSPLIT  16
#define CHUNK   128      /* TSEQ / NSPLIT */
#define NSL     16       /* gemm k-slices */
#define QK_SCALE 0.08838834764831845f  /* 128^-0.5 */

typedef unsigned long long u64;
union U64F2 { u64 u; float2 f; };

__device__ __forceinline__ u64 fma2(u64 a, u64 b, u64 c) {
    u64 d;
    asm("fma.rn.f32x2 %0, %1, %2, %3;" : "=l"(d) : "l"(a), "l"(b), "l"(c));
    return d;
}
__device__ __forceinline__ u64 pack2(float lo, float hi) {
    u64 d;
    asm("mov.b64 %0, {%1, %2};" : "=l"(d) : "f"(lo), "f"(hi));
    return d;
}

// ------------------------- scratch (device globals) -------------------------
__device__ float g_q[BB * NH * HD];            // roped Q   [b][h][d]
__device__ float g_k[BB * NKV * HD];           // roped K @ pos 2047 [b][kv][d]
__device__ float g_v[BB * NKV * HD];           // V       @ pos 2047 [b][kv][d]
__device__ float g_att[BB * DIMM];             // attention output [b][h*128+d]
__device__ float g_part[BB * NH * NSPLIT * HD];
__device__ float g_ml[BB * NH * NSPLIT * 2];   // (m, l) per split
__device__ float g_pqkv[NSL * 32 * 6144];      // qkv gemm partials [s][m][n]
__device__ float g_pout[NSL * 32 * 4096];      // out gemm partials [s][m][n]

// ---------------------------------------------------------------------------
// GEMM v5: out[m][n] = sum_k x[m][k] * w[n][k];  M = 32, K = 4096.
// Thread owns ONE output column n (lane spans n): w row is a private
// register stream (L1-line reuse over 8 kq), x comes from smem as
// LDS.128 BROADCAST (1 crossbar cyc, not 4). Math via fma.rn.f32x2:
// 2 MACs per fma-slot, accumulators are k-parity-packed u64[32].
// Split-K: blockIdx.y = slice (16 x 256k); partials to g_pqkv/g_pout
// [slice][m][n]; no cross-lane reduction, one barrier per CTA.
// ---------------------------------------------------------------------------
template <int MODE>
__global__ __launch_bounds__(128) void gemm_kernel(
    const float* __restrict__ x,
    const float* __restrict__ wq, const float* __restrict__ wk,
    const float* __restrict__ wv)
{
    __shared__ float4 xs4[32 * 64];   // 32 KB: x slice [m][64 float4]

    const int tid   = threadIdx.x;
    const int slice = blockIdx.y;
    const int n     = blockIdx.x * 128 + tid;       // global output column
    const int NTOT  = (MODE == 0) ? 6144 : 4096;

    const float* w; int nr;
    if (MODE == 0) {
        if (n < 4096)      { w = wq; nr = n; }
        else if (n < 5120) { w = wk; nr = n - 4096; }
        else               { w = wv; nr = n - 5120; }
    } else { w = wq; nr = n; }

    const float4* wr = (const float4*)(w + (size_t)nr * 4096 + slice * 256);
    const float4* xg = (const float4*)((MODE == 1) ? (const float*)g_att : x);

    // stage x slice: 32 m x 256 k (2048 float4s, 16 per thread, coalesced)
#pragma unroll
    for (int j = 0; j < 16; j++) {
        int idx = tid + j * 128;
        int m   = idx >> 6;
        int kk  = idx & 63;
        xs4[idx] = xg[m * 1024 + slice * 64 + kk];
    }
    __syncthreads();

    u64 acc[32];
#pragma unroll
    for (int m = 0; m < 32; m++) acc[m] = 0ull;

#pragma unroll 4
    for (int kq = 0; kq < 64; kq++) {
        float4 w4 = wr[kq];
        u64 wlo = pack2(w4.x, w4.y);
        u64 whi = pack2(w4.z, w4.w);
#pragma unroll
        for (int m = 0; m < 32; m++) {
            float4 xv = xs4[m * 64 + kq];     // broadcast LDS.128
            acc[m] = fma2(pack2(xv.x, xv.y), wlo, acc[m]);
            acc[m] = fma2(pack2(xv.z, xv.w), whi, acc[m]);
        }
    }

    float* part = ((MODE == 0) ? g_pqkv : g_pout)
                + (size_t)slice * 32 * NTOT + n;
#pragma unroll
    for (int m = 0; m < 32; m++) {
        U64F2 u; u.u = acc[m];
        part[(size_t)m * NTOT] = u.f.x + u.f.y;   // coalesced across lanes
    }
}

// ---------------------------------------------------------------------------
// Epilogue 0: reduce QKV partials over slices + RoPE -> g_q / g_k / g_v.
// Thread = (m = blockIdx.y, col-pair np). grid (12, 32) x 256.
// ---------------------------------------------------------------------------
__global__ __launch_bounds__(256) void epi0_kernel(
    const float* __restrict__ fc, const float* __restrict__ fs)
{
    const int m  = blockIdx.y;
    const int np = blockIdx.x * 256 + threadIdx.x;   // 0..3071
    const int n0 = np * 2;

    float sx = 0.f, sy = 0.f;
#pragma unroll
    for (int s = 0; s < NSL; s++) {
        float2 v = *(const float2*)&g_pqkv[((size_t)s * 32 + m) * 6144 + n0];
        sx += v.x; sy += v.y;
    }

    if (n0 < 4096) {            // Q + RoPE
        int h = n0 >> 7, d = n0 & 127, i0 = d >> 1;
        float c0 = fc[i0], s0 = fs[i0];
        float2 o = make_float2(sx * c0 - sy * s0, sx * s0 + sy * c0);
        *(float2*)&g_q[(m * NH + h) * HD + d] = o;
    } else if (n0 < 5120) {     // K + RoPE
        int nk = n0 - 4096;
        int h = nk >> 7, d = nk & 127, i0 = d >> 1;
        float c0 = fc[i0], s0 = fs[i0];
        float2 o = make_float2(sx * c0 - sy * s0, sx * s0 + sy * c0);
        *(float2*)&g_k[(m * NKV + h) * HD + d] = o;
    } else {                    // V passthrough
        int nv = n0 - 5120;
        int h = nv >> 7, d = nv & 127;
        *(float2*)&g_v[(m * NKV + h) * HD + d] = make_float2(sx, sy);
    }
}

// ---------------------------------------------------------------------------
// Epilogue 1: reduce out-proj partials -> out. grid (16, 32) x 256.
// ---------------------------------------------------------------------------
__global__ __launch_bounds__(256) void epi1_kernel(float* __restrict__ out)
{
    const int m = blockIdx.y;
    const int n = blockIdx.x * 256 + threadIdx.x;
    float s = 0.f;
#pragma unroll
    for (int sl = 0; sl < NSL; sl++)
        s += g_pout[((size_t)sl * 32 + m) * 4096 + n];
    out[(size_t)m * 4096 + n] = s;
}

// ---------------------------------------------------------------------------
// Split-sequence flash decode. Grid = B*NKV*NSPLIT blocks of 256 threads.
// Phase 1: warp handles 8 positions/iter (32 K-lines in flight), scores
//   reduced with the log-halving tree (31 SHFL per 32 values, result lands
//   one-per-lane -> single STS, no lane-0 bottleneck).
// Phase 3: float4 V loads, stride-8, unroll 8 (deep MLP).
// Position 2047 comes from the freshly roped g_k/g_v (cache row is stale).
// ---------------------------------------------------------------------------
__global__ __launch_bounds__(256) void attn_kernel(
    const float* __restrict__ ck, const float* __restrict__ cv)
{
    __shared__ float  s_sc[4 * CHUNK];     // scores -> exp(p)
    __shared__ float  s_ml[8];
    __shared__ float4 s_red[8 * 4 * 32];   // 16 KB: [pg][h][dquad]

    const int bid   = blockIdx.x;
    const int split = bid % NSPLIT;
    const int kv    = (bid / NSPLIT) % NKV;
    const int b     = bid / (NSPLIT * NKV);
    const int tid   = threadIdx.x;
    const int lane  = tid & 31;
    const int warp  = tid >> 5;
    const int t0    = split * CHUNK;
    const bool last = (split == NSPLIT - 1);
    const int nmain = last ? CHUNK - 1 : CHUNK;

    // ---- phase 1: scores; warp handles 8 positions per outer iteration ----
    const float4* qg = (const float4*)g_q;
    const int qb = (b * NH + kv * 4) * 32;
    float4 q0 = qg[qb + 0 * 32 + lane];
    float4 q1 = qg[qb + 1 * 32 + lane];
    float4 q2 = qg[qb + 2 * 32 + lane];
    float4 q3 = qg[qb + 3 * 32 + lane];

    const float4* kg = (const float4*)ck
                     + (size_t)(b * TSEQ + t0) * (NKV * 32) + kv * 32 + lane;
#pragma unroll
    for (int base = warp * 8; base < CHUNK; base += 64) {
        float4 k4[8];
#pragma unroll
        for (int j = 0; j < 8; j++)
            k4[j] = kg[(size_t)(base + j) * (NKV * 32)];

        float s[32];
#pragma unroll
        for (int j = 0; j < 8; j++) {
            s[j*4+0] = fmaf(k4[j].x, q0.x, fmaf(k4[j].y, q0.y, fmaf(k4[j].z, q0.z, k4[j].w * q0.w)));
            s[j*4+1] = fmaf(k4[j].x, q1.x, fmaf(k4[j].y, q1.y, fmaf(k4[j].z, q1.z, k4[j].w * q1.w)));
            s[j*4+2] = fmaf(k4[j].x, q2.x, fmaf(k4[j].y, q2.y, fmaf(k4[j].z, q2.z, k4[j].w * q2.w)));
            s[j*4+3] = fmaf(k4[j].x, q3.x, fmaf(k4[j].y, q3.y, fmaf(k4[j].z, q3.z, k4[j].w * q3.w)));
        }
        // log-halving tree: lane l ends holding the full sum of value l
#pragma unroll
        for (int step = 16; step >= 1; step >>= 1) {
            bool hi = (lane & step) != 0;
#pragma unroll
            for (int i = 0; i < step; i++) {
                float a = hi ? s[i] : s[i + step];
                float c = hi ? s[i + step] : s[i];
                s[i] = c + __shfl_xor_sync(0xffffffffu, a, step);
            }
        }
        int j = lane >> 2, h = lane & 3;       // value index = j*4 + h = lane
        int pos = base + j;
        if (pos < nmain)
            s_sc[h * CHUNK + pos] = s[0] * QK_SCALE;
    }
    if (last && warp == 7) {   // position 2047 from roped scratch
        const float4* kg2 = (const float4*)g_k;
        float4 k4 = kg2[(b * NKV + kv) * 32 + lane];
        float s0 = q0.x * k4.x + q0.y * k4.y + q0.z * k4.z + q0.w * k4.w;
        float s1 = q1.x * k4.x + q1.y * k4.y + q1.z * k4.z + q1.w * k4.w;
        float s2 = q2.x * k4.x + q2.y * k4.y + q2.z * k4.z + q2.w * k4.w;
        float s3 = q3.x * k4.x + q3.y * k4.y + q3.z * k4.z + q3.w * k4.w;
#pragma unroll
        for (int o = 16; o; o >>= 1) {
            s0 += __shfl_xor_sync(0xffffffffu, s0, o);
            s1 += __shfl_xor_sync(0xffffffffu, s1, o);
            s2 += __shfl_xor_sync(0xffffffffu, s2, o);
            s3 += __shfl_xor_sync(0xffffffffu, s3, o);
        }
        if (lane == 0) {
            s_sc[0 * CHUNK + CHUNK - 1] = s0 * QK_SCALE;
            s_sc[1 * CHUNK + CHUNK - 1] = s1 * QK_SCALE;
            s_sc[2 * CHUNK + CHUNK - 1] = s2 * QK_SCALE;
            s_sc[3 * CHUNK + CHUNK - 1] = s3 * QK_SCALE;
        }
    }
    __syncthreads();

    // ---- phase 2: local softmax (warp r handles row r) ----
    if (warp < 4) {
        float* row = s_sc + warp * CHUNK;
        float v[CHUNK / 32];
        float mx = -1e30f;
#pragma unroll
        for (int j = 0; j < CHUNK / 32; j++) { v[j] = row[lane + 32 * j]; mx = fmaxf(mx, v[j]); }
#pragma unroll
        for (int o = 16; o; o >>= 1) mx = fmaxf(mx, __shfl_xor_sync(0xffffffffu, mx, o));
        float sum = 0.f;
#pragma unroll
        for (int j = 0; j < CHUNK / 32; j++) {
            float p = __expf(v[j] - mx);
            row[lane + 32 * j] = p;
            sum += p;
        }
#pragma unroll
        for (int o = 16; o; o >>= 1) sum += __shfl_xor_sync(0xffffffffu, sum, o);
        if (lane == 0) { s_ml[warp * 2] = mx; s_ml[warp * 2 + 1] = sum; }
    }
    __syncthreads();

    // ---- phase 3: P @ V (warp = pos-group, lane = d-quad) ----
    {
        const int pg = warp;
        const int dq = lane;
        float4 a0 = make_float4(0.f,0.f,0.f,0.f);
        float4 a1 = a0, a2 = a0, a3 = a0;
        const float4* vb = (const float4*)cv
                         + (size_t)(b * TSEQ + t0) * (NKV * 32) + kv * 32 + dq;
        const float* p0r = s_sc + 0 * CHUNK;
        const float* p1r = s_sc + 1 * CHUNK;
        const float* p2r = s_sc + 2 * CHUNK;
        const float* p3r = s_sc + 3 * CHUNK;
#pragma unroll 8
        for (int i = pg; i < nmain; i += 8) {
            float4 v4 = vb[(size_t)i * (NKV * 32)];
            float p0 = p0r[i], p1 = p1r[i], p2 = p2r[i], p3 = p3r[i];
            a0.x = fmaf(p0, v4.x, a0.x); a0.y = fmaf(p0, v4.y, a0.y);
            a0.z = fmaf(p0, v4.z, a0.z); a0.w = fmaf(p0, v4.w, a0.w);
            a1.x = fmaf(p1, v4.x, a1.x); a1.y = fmaf(p1, v4.y, a1.y);
            a1.z = fmaf(p1, v4.z, a1.z); a1.w = fmaf(p1, v4.w, a1.w);
            a2.x = fmaf(p2, v4.x, a2.x); a2.y = fmaf(p2, v4.y, a2.y);
            a2.z = fmaf(p2, v4.z, a2.z); a2.w = fmaf(p2, v4.w, a2.w);
            a3.x = fmaf(p3, v4.x, a3.x); a3.y = fmaf(p3, v4.y, a3.y);
            a3.z = fmaf(p3, v4.z, a3.z); a3.w = fmaf(p3, v4.w, a3.w);
        }
        s_red[(pg * 4 + 0) * 32 + dq] = a0;
        s_red[(pg * 4 + 1) * 32 + dq] = a1;
        s_red[(pg * 4 + 2) * 32 + dq] = a2;
        s_red[(pg * 4 + 3) * 32 + dq] = a3;
    }
    __syncthreads();

    // cross-pos-group reduction + last-position term
    if (tid < 128) {
        const int h  = tid >> 5;
        const int dq = tid & 31;
        float4 s = make_float4(0.f, 0.f, 0.f, 0.f);
#pragma unroll
        for (int pg = 0; pg < 8; pg++) {
            float4 t = s_red[(pg * 4 + h) * 32 + dq];
            s.x += t.x; s.y += t.y; s.z += t.z; s.w += t.w;
        }
        if (last) {
            float4 v4 = ((const float4*)g_v)[(b * NKV + kv) * 32 + dq];
            float p = s_sc[h * CHUNK + CHUNK - 1];
            s.x = fmaf(p, v4.x, s.x); s.y = fmaf(p, v4.y, s.y);
            s.z = fmaf(p, v4.z, s.z); s.w = fmaf(p, v4.w, s.w);
        }
        float4* gp = (float4*)g_part;
        gp[((size_t)(b * NH + kv * 4 + h) * NSPLIT + split) * 32 + dq] = s;
    }
    if (tid < 8) {
        int r = tid >> 1;
        g_ml[((b * NH + kv * 4 + r) * NSPLIT + split) * 2 + (tid & 1)] = s_ml[tid];
    }
}

// ---------------------------------------------------------------------------
// Combine split partials (log-sum-exp). Grid = B*NH blocks of 128 threads.
// ---------------------------------------------------------------------------
__global__ __launch_bounds__(128) void reduce_kernel()
{
    const int hg = blockIdx.x;        // b*NH + h
    const int d  = threadIdx.x;
    float ms[NSPLIT], ls[NSPLIT];
    float m = -1e30f;
#pragma unroll
    for (int i = 0; i < NSPLIT; i++) {
        ms[i] = g_ml[(hg * NSPLIT + i) * 2];
        ls[i] = g_ml[(hg * NSPLIT + i) * 2 + 1];
        m = fmaxf(m, ms[i]);
    }
    float num = 0.f, den = 0.f;
#pragma unroll
    for (int i = 0; i < NSPLIT; i++) {
        float wgt = __expf(ms[i] - m);
        den += wgt * ls[i];
        num += wgt * g_part[((size_t)hg * NSPLIT + i) * HD + d];
    }
    const int b = hg >> 5, h = hg & 31;
    g_att[b * DIMM + h * HD + d] = num / den;
}

// ---------------------------------------------------------------------------
extern "C" void kernel_launch(void* const* d_in, const int* in_sizes, int n_in,
                              void* d_out, int out_size)
{
    const float* x  = (const float*)d_in[0];
    const float* fc = (const float*)d_in[1];
    const float* fs = (const float*)d_in[2];
    const float* wq = (const float*)d_in[3];
    const float* wk = (const float*)d_in[4];
    const float* wv = (const float*)d_in[5];
    const float* wo = (const float*)d_in[6];
    const float* ck = (const float*)d_in[7];
    const float* cv = (const float*)d_in[8];
    float* out = (float*)d_out;

    gemm_kernel<0><<<dim3(48, 16), 128>>>(x, wq, wk, wv);
    epi0_kernel<<<dim3(12, 32), 256>>>(fc, fs);
    attn_kernel<<<BB * NKV * NSPLIT, 256>>>(ck, cv);
    reduce_kernel<<<BB * NH, 128>>>();
    gemm_kernel<1><<<dim3(32, 16), 128>>>(nullptr, wo, nullptr, nullptr);
    epi1_kernel<<<dim3(16, 32), 256>>>(out);
}